// round 15
// baseline (speedup 1.0000x reference)
#include <cuda_runtime.h>
#include <cuda_bf16.h>
#include <math.h>
#include <stdint.h>

// Problem constants (fixed by the reference)
#define NN 50000
#define HH 256
#define TT 4
#define LL 2
#define SS 3
#define CC 3
#define H3 (3 * HH)
#define THX (TT * HH)   // 1024
#define EMAX 1000000
#define NK (TT * NN)    // scatter CSR keys: src*4 + etype (row index into Wh)

// ---------------- fp32 scratch ----------------
#define OFF_H    ((size_t)0)
#define OFF_WH   (OFF_H    + (size_t)NN * HH)      // [NN*THX] Wh (gh aliases)
#define OFF_A    (OFF_WH   + (size_t)NN * THX)     // [NN*HH]  aggregated messages
#define OFF_GX   (OFF_A    + (size_t)NN * HH)      // [NN*H3]
#define OFF_POOL (OFF_GX   + (size_t)NN * H3)      // [HH]
#define SCRATCH_FLOATS (OFF_POOL + HH)
// gh aliases the Wh buffer: Wh dead after scatter, gh produced after.
__device__ float s_scratch[SCRATCH_FLOATS];

// CSR scratch (key = src*4 + etype; payload = dst)
__device__ int s_deg[NK];
__device__ int s_rowptr[NK + 1];
__device__ int s_cursor[NK];
__device__ int s_dlist[EMAX];

// bf16 split weights (original [n][k] layout)
__device__ __nv_bfloat16 s_Whi[(size_t)LL * THX * HH];
__device__ __nv_bfloat16 s_Wlo[(size_t)LL * THX * HH];
__device__ __nv_bfloat16 s_wihi[(size_t)LL * H3 * HH];
__device__ __nv_bfloat16 s_wilo[(size_t)LL * H3 * HH];
__device__ __nv_bfloat16 s_whhi[(size_t)LL * H3 * HH];
__device__ __nv_bfloat16 s_whlo[(size_t)LL * H3 * HH];

// bf16 split activations
__device__ __nv_bfloat16 s_hhi[(size_t)NN * HH];
__device__ __nv_bfloat16 s_hlo[(size_t)NN * HH];
__device__ __nv_bfloat16 s_ahi[(size_t)NN * HH];
__device__ __nv_bfloat16 s_alo[(size_t)NN * HH];

// ---------------- generic helpers ----------------
__global__ void copy_kernel(const float* __restrict__ in, float* __restrict__ out, size_t n4) {
    size_t i = (size_t)blockIdx.x * blockDim.x + threadIdx.x;
    if (i < n4) ((float4*)out)[i] = ((const float4*)in)[i];
}

__global__ void zero_kernel(float* __restrict__ p, size_t n4) {
    size_t i = (size_t)blockIdx.x * blockDim.x + threadIdx.x;
    if (i < n4) ((float4*)p)[i] = make_float4(0.f, 0.f, 0.f, 0.f);
}

__global__ void zero_int_kernel(int* __restrict__ p, int n) {
    int i = blockIdx.x * blockDim.x + threadIdx.x;
    if (i < n) p[i] = 0;
}

__device__ __forceinline__ uint32_t pack_hi2(float x, float y) {
    __nv_bfloat162 p;
    p.x = __float2bfloat16_rn(x);
    p.y = __float2bfloat16_rn(y);
    return *reinterpret_cast<uint32_t*>(&p);
}
__device__ __forceinline__ uint32_t pack_lo2(float x, float y, uint32_t hp) {
    __nv_bfloat162 h = *reinterpret_cast<__nv_bfloat162*>(&hp);
    __nv_bfloat162 p;
    p.x = __float2bfloat16_rn(x - __bfloat162float(h.x));
    p.y = __float2bfloat16_rn(y - __bfloat162float(h.y));
    return *reinterpret_cast<uint32_t*>(&p);
}

__global__ void split_kernel(const float* __restrict__ w, __nv_bfloat16* __restrict__ hi,
                             __nv_bfloat16* __restrict__ lo, int n) {
    int i = blockIdx.x * blockDim.x + threadIdx.x;
    if (i >= n) return;
    float v = w[i];
    __nv_bfloat16 h = __float2bfloat16_rn(v);
    hi[i] = h;
    lo[i] = __float2bfloat16_rn(v - __bfloat162float(h));
}

__global__ void split4_kernel(const float4* __restrict__ in, uint2* __restrict__ hi,
                              uint2* __restrict__ lo, int n4) {
    int i = blockIdx.x * blockDim.x + threadIdx.x;
    if (i >= n4) return;
    float4 v = in[i];
    uint32_t h0 = pack_hi2(v.x, v.y);
    uint32_t h1 = pack_hi2(v.z, v.w);
    hi[i] = make_uint2(h0, h1);
    lo[i] = make_uint2(pack_lo2(v.x, v.y, h0), pack_lo2(v.z, v.w, h1));
}

// ---------------- CSR build (key = src*4 + etype, payload dst) ----------------
__global__ void hist_kernel(const int* __restrict__ src, const int* __restrict__ et,
                            int* __restrict__ deg, int E) {
    int i = blockIdx.x * blockDim.x + threadIdx.x;
    if (i < E) atomicAdd(&deg[src[i] * 4 + et[i]], 1);
}

__global__ void scan_kernel(const int* __restrict__ deg, int* __restrict__ rowptr, int n) {
    __shared__ int buf[1024];
    __shared__ int carry_s;
    int tid = threadIdx.x;
    if (tid == 0) carry_s = 0;
    __syncthreads();
    for (int base = 0; base < n; base += 1024) {
        int v = (base + tid < n) ? deg[base + tid] : 0;
        buf[tid] = v;
        __syncthreads();
        for (int off = 1; off < 1024; off <<= 1) {
            int t = (tid >= off) ? buf[tid - off] : 0;
            __syncthreads();
            buf[tid] += t;
            __syncthreads();
        }
        int carry = carry_s;
        if (base + tid < n) rowptr[base + tid] = carry + buf[tid] - v;
        __syncthreads();
        if (tid == 1023) carry_s = carry + buf[1023];
        __syncthreads();
    }
    if (tid == 0) rowptr[n] = carry_s;
}

__global__ void fill_kernel(const int* __restrict__ src, const int* __restrict__ dst,
                            const int* __restrict__ et, int* __restrict__ cursor,
                            int* __restrict__ dlist, int E) {
    int i = blockIdx.x * blockDim.x + threadIdx.x;
    if (i >= E) return;
    int pos = atomicAdd(&cursor[src[i] * 4 + et[i]], 1);
    dlist[pos] = dst[i];
}

// ---------------- mma helpers ----------------
__device__ __forceinline__ void mma16816(float* c, const uint32_t* a, const uint32_t* b) {
    asm volatile(
        "mma.sync.aligned.m16n8k16.row.col.f32.bf16.bf16.f32 "
        "{%0,%1,%2,%3}, {%4,%5,%6,%7}, {%8,%9}, {%0,%1,%2,%3};"
        : "+f"(c[0]), "+f"(c[1]), "+f"(c[2]), "+f"(c[3])
        : "r"(a[0]), "r"(a[1]), "r"(a[2]), "r"(a[3]), "r"(b[0]), "r"(b[1]));
}

__device__ __forceinline__ void cp_async16(uint32_t smem_addr, const void* gptr) {
    asm volatile("cp.async.ca.shared.global [%0], [%1], 16;"
                 :: "r"(smem_addr), "l"(gptr));
}
__device__ __forceinline__ void cp_async16z(uint32_t smem_addr, const void* gptr, int src_sz) {
    asm volatile("cp.async.ca.shared.global [%0], [%1], 16, %2;"
                 :: "r"(smem_addr), "l"(gptr), "r"(src_sz));
}

// ---------------- bf16x3 tensor-core GEMM, double-buffered cp.async ---------
#define GBM 128
#define GBN 128
#define GBK 32
#define SROW 20
#define STG_U32 (4 * GBM * SROW)
#define DB_AH(s) ((s) * STG_U32 + 0 * GBM * SROW)
#define DB_AL(s) ((s) * STG_U32 + 1 * GBM * SROW)
#define DB_BH(s) ((s) * STG_U32 + 2 * GBM * SROW)
#define DB_BL(s) ((s) * STG_U32 + 3 * GBM * SROW)
#define DB_SMEM_BYTES (2 * STG_U32 * 4)

__global__ __launch_bounds__(256)
void mma_gemm2_kernel(const __nv_bfloat16* __restrict__ Ahi,
                      const __nv_bfloat16* __restrict__ Alo,
                      const __nv_bfloat16* __restrict__ Bhi,
                      const __nv_bfloat16* __restrict__ Blo,
                      const float* __restrict__ bias, float* __restrict__ C,
                      int M, int Nc, int K) {
    extern __shared__ uint32_t sm[];

    const int tid = threadIdx.x;
    const int lane = tid & 31;
    const int wid = tid >> 5;
    const int wm = (wid >> 2) * 64;
    const int wn = (wid & 3) * 32;
    const int g = lane >> 2;
    const int t = lane & 3;

    const int blockRow = blockIdx.y * GBM;
    const int blockCol = blockIdx.x * GBN;
    const int Kw = K >> 1;

    const uint32_t* A32h = (const uint32_t*)Ahi;
    const uint32_t* A32l = (const uint32_t*)Alo;
    const uint32_t* B32h = (const uint32_t*)Bhi;
    const uint32_t* B32l = (const uint32_t*)Blo;

    uint32_t smem_base = (uint32_t)__cvta_generic_to_shared(sm);

    float acc[4][4][4];
#pragma unroll
    for (int mi = 0; mi < 4; mi++)
#pragma unroll
        for (int ni = 0; ni < 4; ni++)
#pragma unroll
            for (int r = 0; r < 4; r++) acc[mi][ni][r] = 0.f;

    auto issue_stage = [&](int k0, int buf) {
#pragma unroll
        for (int i = 0; i < 2; i++) {
            int q = tid + 256 * i;
            int row = q >> 2;
            int ch = q & 3;
            int gm = blockRow + row;
            int sz = (gm < M) ? 16 : 0;
            const uint32_t* sh = A32h + (size_t)gm * Kw + (k0 >> 1) + ch * 4;
            const uint32_t* sl = A32l + (size_t)gm * Kw + (k0 >> 1) + ch * 4;
            uint32_t off = row * SROW + ch * 4;
            cp_async16z(smem_base + (DB_AH(buf) + off) * 4, sh, sz);
            cp_async16z(smem_base + (DB_AL(buf) + off) * 4, sl, sz);
        }
#pragma unroll
        for (int i = 0; i < 2; i++) {
            int q = tid + 256 * i;
            int row = q >> 2;
            int ch = q & 3;
            const uint32_t* sh = B32h + (size_t)(blockCol + row) * Kw + (k0 >> 1) + ch * 4;
            const uint32_t* sl = B32l + (size_t)(blockCol + row) * Kw + (k0 >> 1) + ch * 4;
            uint32_t off = row * SROW + ch * 4;
            cp_async16(smem_base + (DB_BH(buf) + off) * 4, sh);
            cp_async16(smem_base + (DB_BL(buf) + off) * 4, sl);
        }
        asm volatile("cp.async.commit_group;");
    };

    issue_stage(0, 0);
    const int nStages = K / GBK;
    for (int s = 0; s < nStages; s++) {
        if (s + 1 < nStages) {
            issue_stage((s + 1) * GBK, (s + 1) & 1);
            asm volatile("cp.async.wait_group 1;");
        } else {
            asm volatile("cp.async.wait_group 0;");
        }
        __syncthreads();

        const uint32_t* Ash = sm + DB_AH(s & 1);
        const uint32_t* Asl = sm + DB_AL(s & 1);
        const uint32_t* Bsh = sm + DB_BH(s & 1);
        const uint32_t* Bsl = sm + DB_BL(s & 1);

#pragma unroll
        for (int ks = 0; ks < 2; ks++) {
            const int base = ks * 8;
            uint32_t ah[4][4], al[4][4], bh_[4][2], bl_[4][2];
#pragma unroll
            for (int mi = 0; mi < 4; mi++) {
                int r0 = (wm + mi * 16 + g) * SROW;
                ah[mi][0] = Ash[r0 + base + t];
                ah[mi][1] = Ash[r0 + 8 * SROW + base + t];
                ah[mi][2] = Ash[r0 + base + t + 4];
                ah[mi][3] = Ash[r0 + 8 * SROW + base + t + 4];
                al[mi][0] = Asl[r0 + base + t];
                al[mi][1] = Asl[r0 + 8 * SROW + base + t];
                al[mi][2] = Asl[r0 + base + t + 4];
                al[mi][3] = Asl[r0 + 8 * SROW + base + t + 4];
            }
#pragma unroll
            for (int ni = 0; ni < 4; ni++) {
                int n0 = (wn + ni * 8 + g) * SROW;
                bh_[ni][0] = Bsh[n0 + base + t];
                bh_[ni][1] = Bsh[n0 + base + t + 4];
                bl_[ni][0] = Bsl[n0 + base + t];
                bl_[ni][1] = Bsl[n0 + base + t + 4];
            }
#pragma unroll
            for (int mi = 0; mi < 4; mi++)
#pragma unroll
                for (int ni = 0; ni < 4; ni++) {
                    mma16816(acc[mi][ni], ah[mi], bh_[ni]);
                    mma16816(acc[mi][ni], ah[mi], bl_[ni]);
                    mma16816(acc[mi][ni], al[mi], bh_[ni]);
                }
        }
        __syncthreads();
    }

#pragma unroll
    for (int mi = 0; mi < 4; mi++) {
        int r0 = blockRow + wm + mi * 16 + g;
        int r1 = r0 + 8;
#pragma unroll
        for (int ni = 0; ni < 4; ni++) {
            int col = blockCol + wn + ni * 8 + t * 2;
            float b0 = bias ? bias[col] : 0.f;
            float b1 = bias ? bias[col + 1] : 0.f;
            if (r0 < M) {
                float2 v = make_float2(acc[mi][ni][0] + b0, acc[mi][ni][1] + b1);
                *(float2*)&C[(size_t)r0 * Nc + col] = v;
            }
            if (r1 < M) {
                float2 v = make_float2(acc[mi][ni][2] + b0, acc[mi][ni][3] + b1);
                *(float2*)&C[(size_t)r1 * Nc + col] = v;
            }
        }
    }
}

// ---------------- src-ordered scatter: sequential Wh reads, atomic a writes --
// warp per key (src*4+etype): read Wh row once (sequential over Wh), then
// red.global.add into a[dst] for each out-edge (a is 51MB, L2-resident).
__global__ void scatter_src_kernel(const float* __restrict__ Wh,
                                   const int* __restrict__ rowptr,
                                   const int* __restrict__ dlist,
                                   float* __restrict__ a, int nk) {
    int warp = (int)(((size_t)blockIdx.x * blockDim.x + threadIdx.x) >> 5);
    int lane = threadIdx.x & 31;
    if (warp >= nk) return;
    int p = rowptr[warp];
    int p1 = rowptr[warp + 1];
    if (p == p1) return;
    // Wh row for key = src*4+et is exactly Wh + key*HH (since THX = 4*HH)
    const float4* sp = (const float4*)(Wh + (size_t)warp * HH);
    float4 v0 = sp[lane];
    float4 v1 = sp[lane + 32];
    for (; p < p1; p++) {
        int d = __ldg(&dlist[p]);
        float4* dp = (float4*)(a + (size_t)d * HH);
        asm volatile("red.global.add.v4.f32 [%0], {%1,%2,%3,%4};"
                     :: "l"(dp + lane), "f"(v0.x), "f"(v0.y), "f"(v0.z), "f"(v0.w)
                     : "memory");
        asm volatile("red.global.add.v4.f32 [%0], {%1,%2,%3,%4};"
                     :: "l"(dp + lane + 32), "f"(v1.x), "f"(v1.y), "f"(v1.z), "f"(v1.w)
                     : "memory");
    }
}

// ---------------- fast transcendentals ----------------
__device__ __forceinline__ float sigmoid_fast(float x) {
    return __fdividef(1.f, 1.f + __expf(-x));
}
__device__ __forceinline__ float tanh_fast(float x) {
    // 1 - 2/(e^{2x}+1); saturates correctly at +-1, no NaN
    return 1.f - __fdividef(2.f, __expf(2.f * x) + 1.f);
}

// ---------------- GRU gates: writes h fp32 AND h_hi/h_lo bf16 ----------------
__global__ void gru_kernel(const float4* __restrict__ gx, const float4* __restrict__ gh,
                           float4* __restrict__ h,
                           uint2* __restrict__ hhi, uint2* __restrict__ hlo, int total4) {
    int idx = blockIdx.x * blockDim.x + threadIdx.x;
    if (idx >= total4) return;
    int n = idx >> 6;
    int k = idx & 63;
    const float4* gxr = gx + (size_t)n * 192;
    const float4* ghr = gh + (size_t)n * 192;
    float4 xr = gxr[k], xz = gxr[64 + k], xn = gxr[128 + k];
    float4 hr = ghr[k], hz = ghr[64 + k], hn = ghr[128 + k];
    float4 hv = h[idx];
    float4 out;
#define GRU1(c)                                                       \
    {                                                                 \
        float r = sigmoid_fast(xr.c + hr.c);                          \
        float z = sigmoid_fast(xz.c + hz.c);                          \
        float nng = tanh_fast(xn.c + r * hn.c);                       \
        out.c = (1.f - z) * nng + z * hv.c;                           \
    }
    GRU1(x) GRU1(y) GRU1(z) GRU1(w)
#undef GRU1
    h[idx] = out;
    uint32_t h0 = pack_hi2(out.x, out.y);
    uint32_t h1 = pack_hi2(out.z, out.w);
    hhi[idx] = make_uint2(h0, h1);
    hlo[idx] = make_uint2(pack_lo2(out.x, out.y, h0), pack_lo2(out.z, out.w, h1));
}

// ---------------- pooling + FC ----------------
__global__ void pool_kernel(const float* __restrict__ h, float* __restrict__ pooled, int n) {
    int k = threadIdx.x;
    float acc = 0.f;
    for (int r = blockIdx.x; r < n; r += gridDim.x)
        acc += h[(size_t)r * HH + k];
    atomicAdd(&pooled[k], acc);
}

__global__ void fc_kernel(const float* __restrict__ pooled, const float* __restrict__ fc_w,
                          const float* __restrict__ fc_b, float* __restrict__ out, float invN) {
    int c = blockIdx.x;
    int lane = threadIdx.x;
    float acc = 0.f;
    for (int k = lane; k < HH; k += 32) acc += pooled[k] * fc_w[c * HH + k];
#pragma unroll
    for (int o = 16; o; o >>= 1) acc += __shfl_xor_sync(0xffffffffu, acc, o);
    if (lane == 0) out[c] = acc * invN + fc_b[c];
}

// ---------------- host orchestration ----------------
extern "C" void kernel_launch(void* const* d_in, const int* in_sizes, int n_in,
                              void* d_out, int out_size) {
    const float* x      = (const float*)d_in[0];
    const int*   src    = (const int*)d_in[1];
    const int*   dst    = (const int*)d_in[2];
    const int*   etype  = (const int*)d_in[3];
    const float* W_lin  = (const float*)d_in[4];
    const float* b_lin  = (const float*)d_in[5];
    const float* w_ih   = (const float*)d_in[6];
    const float* w_hh   = (const float*)d_in[7];
    const float* b_ih   = (const float*)d_in[8];
    const float* b_hh   = (const float*)d_in[9];
    const float* fc_w   = (const float*)d_in[10];
    const float* fc_b   = (const float*)d_in[11];
    float* out = (float*)d_out;

    const int E = in_sizes[1];

    cudaFuncSetAttribute(mma_gemm2_kernel,
                         cudaFuncAttributeMaxDynamicSharedMemorySize, DB_SMEM_BYTES);

    float* base = nullptr;
    cudaGetSymbolAddress((void**)&base, s_scratch);
    float* p_h      = base + OFF_H;
    float* p_Wh     = base + OFF_WH;
    float* p_gh     = base + OFF_WH;   // alias: Wh dead after scatter
    float* p_a      = base + OFF_A;
    float* p_gx     = base + OFF_GX;
    float* p_pooled = base + OFF_POOL;

    int *p_deg, *p_rowptr, *p_cursor, *p_dlist;
    cudaGetSymbolAddress((void**)&p_deg, s_deg);
    cudaGetSymbolAddress((void**)&p_rowptr, s_rowptr);
    cudaGetSymbolAddress((void**)&p_cursor, s_cursor);
    cudaGetSymbolAddress((void**)&p_dlist, s_dlist);

    __nv_bfloat16 *p_Whi, *p_Wlo, *p_wihi, *p_wilo, *p_whhi, *p_whlo;
    __nv_bfloat16 *p_hhi, *p_hlo, *p_ahi, *p_alo;
    cudaGetSymbolAddress((void**)&p_Whi, s_Whi);
    cudaGetSymbolAddress((void**)&p_Wlo, s_Wlo);
    cudaGetSymbolAddress((void**)&p_wihi, s_wihi);
    cudaGetSymbolAddress((void**)&p_wilo, s_wilo);
    cudaGetSymbolAddress((void**)&p_whhi, s_whhi);
    cudaGetSymbolAddress((void**)&p_whlo, s_whlo);
    cudaGetSymbolAddress((void**)&p_hhi, s_hhi);
    cudaGetSymbolAddress((void**)&p_hlo, s_hlo);
    cudaGetSymbolAddress((void**)&p_ahi, s_ahi);
    cudaGetSymbolAddress((void**)&p_alo, s_alo);

    // ---- weight splits ----
    {
        int nW = LL * THX * HH;
        int nG = LL * H3 * HH;
        split_kernel<<<(nW + 255) / 256, 256>>>(W_lin, p_Whi, p_Wlo, nW);
        split_kernel<<<(nG + 255) / 256, 256>>>(w_ih, p_wihi, p_wilo, nG);
        split_kernel<<<(nG + 255) / 256, 256>>>(w_hh, p_whhi, p_whlo, nG);
    }

    // ---- CSR build (key = src*4 + etype; payload dst) ----
    zero_int_kernel<<<(NK + 255) / 256, 256>>>(p_deg, NK);
    hist_kernel<<<(E + 255) / 256, 256>>>(src, etype, p_deg, E);
    scan_kernel<<<1, 1024>>>(p_deg, p_rowptr, NK);
    cudaMemcpyAsync(p_cursor, p_rowptr, NK * sizeof(int), cudaMemcpyDeviceToDevice);
    fill_kernel<<<(E + 255) / 256, 256>>>(src, dst, etype, p_cursor, p_dlist, E);

    // ---- h = x ; h_hi/h_lo = split(x) ----
    size_t n4 = (size_t)NN * HH / 4;
    copy_kernel<<<(int)((n4 + 255) / 256), 256>>>(x, p_h, n4);
    split4_kernel<<<(int)((n4 + 255) / 256), 256>>>((const float4*)x, (uint2*)p_hhi,
                                                    (uint2*)p_hlo, (int)n4);

    dim3 grid_wh(THX / GBN, (NN + GBM - 1) / GBM);   // (8, 391)
    dim3 grid_g(H3 / GBN, (NN + GBM - 1) / GBM);     // (6, 391)
    int scatter_blocks = (int)(((size_t)NK * 32 + 255) / 256);
    int gru_blocks = (int)((n4 + 255) / 256);

    for (int l = 0; l < LL; l++) {
        const float* blinL = b_lin + (size_t)l * THX;
        const float* bihL  = b_ih + (size_t)l * H3;
        const float* bhhL  = b_hh + (size_t)l * H3;
        const __nv_bfloat16* Whl  = p_Whi + (size_t)l * THX * HH;
        const __nv_bfloat16* Wll  = p_Wlo + (size_t)l * THX * HH;
        const __nv_bfloat16* wihl = p_wihi + (size_t)l * H3 * HH;
        const __nv_bfloat16* will = p_wilo + (size_t)l * H3 * HH;
        const __nv_bfloat16* whhl = p_whhi + (size_t)l * H3 * HH;
        const __nv_bfloat16* whll = p_whlo + (size_t)l * H3 * HH;

        for (int s = 0; s < SS; s++) {
            // Wh = h @ W^T + b_lin   [N, T*H]
            mma_gemm2_kernel<<<grid_wh, 256, DB_SMEM_BYTES>>>(
                p_hhi, p_hlo, Whl, Wll, blinL, p_Wh, NN, THX, HH);
            // a = 0 ; scatter: sequential Wh reads, atomic adds into a[dst]
            zero_kernel<<<(int)((n4 + 255) / 256), 256>>>(p_a, n4);
            scatter_src_kernel<<<scatter_blocks, 256>>>(p_Wh, p_rowptr, p_dlist, p_a, NK);
            // a_hi/a_lo = split(a)
            split4_kernel<<<(int)((n4 + 255) / 256), 256>>>((const float4*)p_a,
                                                            (uint2*)p_ahi, (uint2*)p_alo,
                                                            (int)n4);
            // gx = a @ w_ih^T + b_ih ; gh = h @ w_hh^T + b_hh (gh overwrites Wh)
            mma_gemm2_kernel<<<grid_g, 256, DB_SMEM_BYTES>>>(
                p_ahi, p_alo, wihl, will, bihL, p_gx, NN, H3, HH);
            mma_gemm2_kernel<<<grid_g, 256, DB_SMEM_BYTES>>>(
                p_hhi, p_hlo, whhl, whll, bhhL, p_gh, NN, H3, HH);
            // GRU gates: h fp32 in-place + h_hi/h_lo for next step's GEMMs
            gru_kernel<<<gru_blocks, 256>>>((const float4*)p_gx, (const float4*)p_gh,
                                            (float4*)p_h, (uint2*)p_hhi, (uint2*)p_hlo,
                                            (int)n4);
        }
    }

    // pooled mean + FC
    zero_kernel<<<1, 64>>>(p_pooled, HH / 4);
    pool_kernel<<<256, HH>>>(p_h, p_pooled, NN);
    fc_kernel<<<CC, 32>>>(p_pooled, fc_w, fc_b, out, 1.0f / (float)NN);
}

// round 16
// speedup vs baseline: 1.0932x; 1.0932x over previous
#include <cuda_runtime.h>
#include <cuda_bf16.h>
#include <math.h>
#include <stdint.h>

// Problem constants (fixed by the reference)
#define NN 50000
#define HH 256
#define TT 4
#define LL 2
#define SS 3
#define CC 3
#define H3 (3 * HH)
#define THX (TT * HH)   // 1024
#define EMAX 1000000

// ---------------- fp32 scratch ----------------
#define OFF_H    ((size_t)0)
#define OFF_WH   (OFF_H    + (size_t)NN * HH)      // [NN*THX] Wh (gh aliases)
#define OFF_GX   (OFF_WH   + (size_t)NN * THX)     // [NN*H3]
#define OFF_POOL (OFF_GX   + (size_t)NN * H3)      // [HH]
#define SCRATCH_FLOATS (OFF_POOL + HH)
// gh aliases the Wh buffer: Wh dead after gather, gh produced after.
__device__ float s_scratch[SCRATCH_FLOATS];

// CSR scratch
__device__ int s_deg[NN];
__device__ int s_rowptr[NN + 1];
__device__ int s_cursor[NN];
__device__ int s_eidx[EMAX];       // packed src*4 + etype, grouped by dst

// bf16 split weights (original [n][k] layout)
__device__ __nv_bfloat16 s_Whi[(size_t)LL * THX * HH];
__device__ __nv_bfloat16 s_Wlo[(size_t)LL * THX * HH];
__device__ __nv_bfloat16 s_wihi[(size_t)LL * H3 * HH];
__device__ __nv_bfloat16 s_wilo[(size_t)LL * H3 * HH];
__device__ __nv_bfloat16 s_whhi[(size_t)LL * H3 * HH];
__device__ __nv_bfloat16 s_whlo[(size_t)LL * H3 * HH];

// bf16 split activations (produced by GRU / gather directly)
__device__ __nv_bfloat16 s_hhi[(size_t)NN * HH];
__device__ __nv_bfloat16 s_hlo[(size_t)NN * HH];
__device__ __nv_bfloat16 s_ahi[(size_t)NN * HH];
__device__ __nv_bfloat16 s_alo[(size_t)NN * HH];

// ---------------- generic helpers ----------------
__global__ void copy_kernel(const float* __restrict__ in, float* __restrict__ out, size_t n4) {
    size_t i = (size_t)blockIdx.x * blockDim.x + threadIdx.x;
    if (i < n4) ((float4*)out)[i] = ((const float4*)in)[i];
}

__global__ void zero_kernel(float* __restrict__ p, size_t n4) {
    size_t i = (size_t)blockIdx.x * blockDim.x + threadIdx.x;
    if (i < n4) ((float4*)p)[i] = make_float4(0.f, 0.f, 0.f, 0.f);
}

__global__ void zero_int_kernel(int* __restrict__ p, int n) {
    int i = blockIdx.x * blockDim.x + threadIdx.x;
    if (i < n) p[i] = 0;
}

__device__ __forceinline__ uint32_t pack_hi2(float x, float y) {
    __nv_bfloat162 p;
    p.x = __float2bfloat16_rn(x);
    p.y = __float2bfloat16_rn(y);
    return *reinterpret_cast<uint32_t*>(&p);
}
__device__ __forceinline__ uint32_t pack_lo2(float x, float y, uint32_t hp) {
    __nv_bfloat162 h = *reinterpret_cast<__nv_bfloat162*>(&hp);
    __nv_bfloat162 p;
    p.x = __float2bfloat16_rn(x - __bfloat162float(h.x));
    p.y = __float2bfloat16_rn(y - __bfloat162float(h.y));
    return *reinterpret_cast<uint32_t*>(&p);
}

__global__ void split_kernel(const float* __restrict__ w, __nv_bfloat16* __restrict__ hi,
                             __nv_bfloat16* __restrict__ lo, int n) {
    int i = blockIdx.x * blockDim.x + threadIdx.x;
    if (i >= n) return;
    float v = w[i];
    __nv_bfloat16 h = __float2bfloat16_rn(v);
    hi[i] = h;
    lo[i] = __float2bfloat16_rn(v - __bfloat162float(h));
}

__global__ void split4_kernel(const float4* __restrict__ in, uint2* __restrict__ hi,
                              uint2* __restrict__ lo, int n4) {
    int i = blockIdx.x * blockDim.x + threadIdx.x;
    if (i >= n4) return;
    float4 v = in[i];
    uint32_t h0 = pack_hi2(v.x, v.y);
    uint32_t h1 = pack_hi2(v.z, v.w);
    hi[i] = make_uint2(h0, h1);
    lo[i] = make_uint2(pack_lo2(v.x, v.y, h0), pack_lo2(v.z, v.w, h1));
}

// ---------------- CSR build ----------------
__global__ void hist_kernel(const int* __restrict__ dst, int* __restrict__ deg, int E) {
    int i = blockIdx.x * blockDim.x + threadIdx.x;
    if (i < E) atomicAdd(&deg[dst[i]], 1);
}

__global__ void scan_kernel(const int* __restrict__ deg, int* __restrict__ rowptr, int n) {
    __shared__ int buf[1024];
    __shared__ int carry_s;
    int tid = threadIdx.x;
    if (tid == 0) carry_s = 0;
    __syncthreads();
    for (int base = 0; base < n; base += 1024) {
        int v = (base + tid < n) ? deg[base + tid] : 0;
        buf[tid] = v;
        __syncthreads();
        for (int off = 1; off < 1024; off <<= 1) {
            int t = (tid >= off) ? buf[tid - off] : 0;
            __syncthreads();
            buf[tid] += t;
            __syncthreads();
        }
        int carry = carry_s;
        if (base + tid < n) rowptr[base + tid] = carry + buf[tid] - v;
        __syncthreads();
        if (tid == 1023) carry_s = carry + buf[1023];
        __syncthreads();
    }
    if (tid == 0) rowptr[n] = carry_s;
}

__global__ void fill_kernel(const int* __restrict__ src, const int* __restrict__ dst,
                            const int* __restrict__ et, int* __restrict__ cursor,
                            int* __restrict__ eidx, int E) {
    int i = blockIdx.x * blockDim.x + threadIdx.x;
    if (i >= E) return;
    int pos = atomicAdd(&cursor[dst[i]], 1);
    eidx[pos] = src[i] * 4 + et[i];
}

// ---------------- mma helpers ----------------
__device__ __forceinline__ void mma16816(float* c, const uint32_t* a, const uint32_t* b) {
    asm volatile(
        "mma.sync.aligned.m16n8k16.row.col.f32.bf16.bf16.f32 "
        "{%0,%1,%2,%3}, {%4,%5,%6,%7}, {%8,%9}, {%0,%1,%2,%3};"
        : "+f"(c[0]), "+f"(c[1]), "+f"(c[2]), "+f"(c[3])
        : "r"(a[0]), "r"(a[1]), "r"(a[2]), "r"(a[3]), "r"(b[0]), "r"(b[1]));
}

__device__ __forceinline__ void cp_async16(uint32_t smem_addr, const void* gptr) {
    asm volatile("cp.async.ca.shared.global [%0], [%1], 16;"
                 :: "r"(smem_addr), "l"(gptr));
}
__device__ __forceinline__ void cp_async16z(uint32_t smem_addr, const void* gptr, int src_sz) {
    asm volatile("cp.async.ca.shared.global [%0], [%1], 16, %2;"
                 :: "r"(smem_addr), "l"(gptr), "r"(src_sz));
}

// ---------------- bf16x3 tensor-core GEMM, double-buffered cp.async ---------
#define GBM 128
#define GBN 128
#define GBK 32
#define SROW 20
#define STG_U32 (4 * GBM * SROW)
#define DB_AH(s) ((s) * STG_U32 + 0 * GBM * SROW)
#define DB_AL(s) ((s) * STG_U32 + 1 * GBM * SROW)
#define DB_BH(s) ((s) * STG_U32 + 2 * GBM * SROW)
#define DB_BL(s) ((s) * STG_U32 + 3 * GBM * SROW)
#define DB_SMEM_BYTES (2 * STG_U32 * 4)

__global__ __launch_bounds__(256)
void mma_gemm2_kernel(const __nv_bfloat16* __restrict__ Ahi,
                      const __nv_bfloat16* __restrict__ Alo,
                      const __nv_bfloat16* __restrict__ Bhi,
                      const __nv_bfloat16* __restrict__ Blo,
                      const float* __restrict__ bias, float* __restrict__ C,
                      int M, int Nc, int K) {
    extern __shared__ uint32_t sm[];

    const int tid = threadIdx.x;
    const int lane = tid & 31;
    const int wid = tid >> 5;
    const int wm = (wid >> 2) * 64;
    const int wn = (wid & 3) * 32;
    const int g = lane >> 2;
    const int t = lane & 3;

    const int blockRow = blockIdx.y * GBM;
    const int blockCol = blockIdx.x * GBN;
    const int Kw = K >> 1;

    const uint32_t* A32h = (const uint32_t*)Ahi;
    const uint32_t* A32l = (const uint32_t*)Alo;
    const uint32_t* B32h = (const uint32_t*)Bhi;
    const uint32_t* B32l = (const uint32_t*)Blo;

    uint32_t smem_base = (uint32_t)__cvta_generic_to_shared(sm);

    float acc[4][4][4];
#pragma unroll
    for (int mi = 0; mi < 4; mi++)
#pragma unroll
        for (int ni = 0; ni < 4; ni++)
#pragma unroll
            for (int r = 0; r < 4; r++) acc[mi][ni][r] = 0.f;

    auto issue_stage = [&](int k0, int buf) {
#pragma unroll
        for (int i = 0; i < 2; i++) {
            int q = tid + 256 * i;
            int row = q >> 2;
            int ch = q & 3;
            int gm = blockRow + row;
            int sz = (gm < M) ? 16 : 0;
            const uint32_t* sh = A32h + (size_t)gm * Kw + (k0 >> 1) + ch * 4;
            const uint32_t* sl = A32l + (size_t)gm * Kw + (k0 >> 1) + ch * 4;
            uint32_t off = row * SROW + ch * 4;
            cp_async16z(smem_base + (DB_AH(buf) + off) * 4, sh, sz);
            cp_async16z(smem_base + (DB_AL(buf) + off) * 4, sl, sz);
        }
#pragma unroll
        for (int i = 0; i < 2; i++) {
            int q = tid + 256 * i;
            int row = q >> 2;
            int ch = q & 3;
            const uint32_t* sh = B32h + (size_t)(blockCol + row) * Kw + (k0 >> 1) + ch * 4;
            const uint32_t* sl = B32l + (size_t)(blockCol + row) * Kw + (k0 >> 1) + ch * 4;
            uint32_t off = row * SROW + ch * 4;
            cp_async16(smem_base + (DB_BH(buf) + off) * 4, sh);
            cp_async16(smem_base + (DB_BL(buf) + off) * 4, sl);
        }
        asm volatile("cp.async.commit_group;");
    };

    issue_stage(0, 0);
    const int nStages = K / GBK;
    for (int s = 0; s < nStages; s++) {
        if (s + 1 < nStages) {
            issue_stage((s + 1) * GBK, (s + 1) & 1);
            asm volatile("cp.async.wait_group 1;");
        } else {
            asm volatile("cp.async.wait_group 0;");
        }
        __syncthreads();

        const uint32_t* Ash = sm + DB_AH(s & 1);
        const uint32_t* Asl = sm + DB_AL(s & 1);
        const uint32_t* Bsh = sm + DB_BH(s & 1);
        const uint32_t* Bsl = sm + DB_BL(s & 1);

#pragma unroll
        for (int ks = 0; ks < 2; ks++) {
            const int base = ks * 8;
            uint32_t ah[4][4], al[4][4], bh_[4][2], bl_[4][2];
#pragma unroll
            for (int mi = 0; mi < 4; mi++) {
                int r0 = (wm + mi * 16 + g) * SROW;
                ah[mi][0] = Ash[r0 + base + t];
                ah[mi][1] = Ash[r0 + 8 * SROW + base + t];
                ah[mi][2] = Ash[r0 + base + t + 4];
                ah[mi][3] = Ash[r0 + 8 * SROW + base + t + 4];
                al[mi][0] = Asl[r0 + base + t];
                al[mi][1] = Asl[r0 + 8 * SROW + base + t];
                al[mi][2] = Asl[r0 + base + t + 4];
                al[mi][3] = Asl[r0 + 8 * SROW + base + t + 4];
            }
#pragma unroll
            for (int ni = 0; ni < 4; ni++) {
                int n0 = (wn + ni * 8 + g) * SROW;
                bh_[ni][0] = Bsh[n0 + base + t];
                bh_[ni][1] = Bsh[n0 + base + t + 4];
                bl_[ni][0] = Bsl[n0 + base + t];
                bl_[ni][1] = Bsl[n0 + base + t + 4];
            }
#pragma unroll
            for (int mi = 0; mi < 4; mi++)
#pragma unroll
                for (int ni = 0; ni < 4; ni++) {
                    mma16816(acc[mi][ni], ah[mi], bh_[ni]);
                    mma16816(acc[mi][ni], ah[mi], bl_[ni]);
                    mma16816(acc[mi][ni], al[mi], bh_[ni]);
                }
        }
        __syncthreads();
    }

#pragma unroll
    for (int mi = 0; mi < 4; mi++) {
        int r0 = blockRow + wm + mi * 16 + g;
        int r1 = r0 + 8;
#pragma unroll
        for (int ni = 0; ni < 4; ni++) {
            int col = blockCol + wn + ni * 8 + t * 2;
            float b0 = bias ? bias[col] : 0.f;
            float b1 = bias ? bias[col + 1] : 0.f;
            if (r0 < M) {
                float2 v = make_float2(acc[mi][ni][0] + b0, acc[mi][ni][1] + b1);
                *(float2*)&C[(size_t)r0 * Nc + col] = v;
            }
            if (r1 < M) {
                float2 v = make_float2(acc[mi][ni][2] + b0, acc[mi][ni][3] + b1);
                *(float2*)&C[(size_t)r1 * Nc + col] = v;
            }
        }
    }
}

// ---------------- CSR gather -> bf16 hi/lo directly ----------------
__global__ void gather_kernel(const float* __restrict__ Wh,
                              const int* __restrict__ rowptr,
                              const int* __restrict__ eidx,
                              uint2* __restrict__ ahi, uint2* __restrict__ alo, int n) {
    int warp = (int)(((size_t)blockIdx.x * blockDim.x + threadIdx.x) >> 5);
    int lane = threadIdx.x & 31;
    if (warp >= n) return;
    int p = rowptr[warp];
    int p1 = rowptr[warp + 1];
    float4 acc0 = make_float4(0.f, 0.f, 0.f, 0.f);
    float4 acc1 = make_float4(0.f, 0.f, 0.f, 0.f);
    for (; p + 1 < p1; p += 2) {
        int e0 = __ldg(&eidx[p]);
        int e1 = __ldg(&eidx[p + 1]);
        const float4* s0 = (const float4*)(Wh + (size_t)(e0 >> 2) * THX + (size_t)(e0 & 3) * HH);
        const float4* s1 = (const float4*)(Wh + (size_t)(e1 >> 2) * THX + (size_t)(e1 & 3) * HH);
        float4 v00 = s0[lane], v01 = s0[lane + 32];
        float4 v10 = s1[lane], v11 = s1[lane + 32];
        acc0.x += v00.x + v10.x; acc0.y += v00.y + v10.y;
        acc0.z += v00.z + v10.z; acc0.w += v00.w + v10.w;
        acc1.x += v01.x + v11.x; acc1.y += v01.y + v11.y;
        acc1.z += v01.z + v11.z; acc1.w += v01.w + v11.w;
    }
    if (p < p1) {
        int e0 = __ldg(&eidx[p]);
        const float4* s0 = (const float4*)(Wh + (size_t)(e0 >> 2) * THX + (size_t)(e0 & 3) * HH);
        float4 v00 = s0[lane], v01 = s0[lane + 32];
        acc0.x += v00.x; acc0.y += v00.y; acc0.z += v00.z; acc0.w += v00.w;
        acc1.x += v01.x; acc1.y += v01.y; acc1.z += v01.z; acc1.w += v01.w;
    }
    size_t rowbase = (size_t)warp * 64;
    uint32_t h0 = pack_hi2(acc0.x, acc0.y);
    uint32_t h1 = pack_hi2(acc0.z, acc0.w);
    ahi[rowbase + lane] = make_uint2(h0, h1);
    alo[rowbase + lane] = make_uint2(pack_lo2(acc0.x, acc0.y, h0), pack_lo2(acc0.z, acc0.w, h1));
    uint32_t h2 = pack_hi2(acc1.x, acc1.y);
    uint32_t h3 = pack_hi2(acc1.z, acc1.w);
    ahi[rowbase + lane + 32] = make_uint2(h2, h3);
    alo[rowbase + lane + 32] = make_uint2(pack_lo2(acc1.x, acc1.y, h2), pack_lo2(acc1.z, acc1.w, h3));
}

// ---------------- fast transcendentals ----------------
__device__ __forceinline__ float sigmoid_fast(float x) {
    return __fdividef(1.f, 1.f + __expf(-x));
}
__device__ __forceinline__ float tanh_fast(float x) {
    // 1 - 2/(e^{2x}+1); saturates correctly at +-1, no NaN
    return 1.f - __fdividef(2.f, __expf(2.f * x) + 1.f);
}

// ---------------- GRU gates: writes h fp32 AND h_hi/h_lo bf16 ----------------
__global__ void gru_kernel(const float4* __restrict__ gx, const float4* __restrict__ gh,
                           float4* __restrict__ h,
                           uint2* __restrict__ hhi, uint2* __restrict__ hlo, int total4) {
    int idx = blockIdx.x * blockDim.x + threadIdx.x;
    if (idx >= total4) return;
    int n = idx >> 6;
    int k = idx & 63;
    const float4* gxr = gx + (size_t)n * 192;
    const float4* ghr = gh + (size_t)n * 192;
    float4 xr = gxr[k], xz = gxr[64 + k], xn = gxr[128 + k];
    float4 hr = ghr[k], hz = ghr[64 + k], hn = ghr[128 + k];
    float4 hv = h[idx];
    float4 out;
#define GRU1(c)                                                       \
    {                                                                 \
        float r = sigmoid_fast(xr.c + hr.c);                          \
        float z = sigmoid_fast(xz.c + hz.c);                          \
        float nng = tanh_fast(xn.c + r * hn.c);                       \
        out.c = (1.f - z) * nng + z * hv.c;                           \
    }
    GRU1(x) GRU1(y) GRU1(z) GRU1(w)
#undef GRU1
    h[idx] = out;
    uint32_t h0 = pack_hi2(out.x, out.y);
    uint32_t h1 = pack_hi2(out.z, out.w);
    hhi[idx] = make_uint2(h0, h1);
    hlo[idx] = make_uint2(pack_lo2(out.x, out.y, h0), pack_lo2(out.z, out.w, h1));
}

// ---------------- pooling + FC ----------------
__global__ void pool_kernel(const float* __restrict__ h, float* __restrict__ pooled, int n) {
    int k = threadIdx.x;
    float acc = 0.f;
    for (int r = blockIdx.x; r < n; r += gridDim.x)
        acc += h[(size_t)r * HH + k];
    atomicAdd(&pooled[k], acc);
}

__global__ void fc_kernel(const float* __restrict__ pooled, const float* __restrict__ fc_w,
                          const float* __restrict__ fc_b, float* __restrict__ out, float invN) {
    int c = blockIdx.x;
    int lane = threadIdx.x;
    float acc = 0.f;
    for (int k = lane; k < HH; k += 32) acc += pooled[k] * fc_w[c * HH + k];
#pragma unroll
    for (int o = 16; o; o >>= 1) acc += __shfl_xor_sync(0xffffffffu, acc, o);
    if (lane == 0) out[c] = acc * invN + fc_b[c];
}

// ---------------- host orchestration ----------------
extern "C" void kernel_launch(void* const* d_in, const int* in_sizes, int n_in,
                              void* d_out, int out_size) {
    const float* x      = (const float*)d_in[0];
    const int*   src    = (const int*)d_in[1];
    const int*   dst    = (const int*)d_in[2];
    const int*   etype  = (const int*)d_in[3];
    const float* W_lin  = (const float*)d_in[4];
    const float* b_lin  = (const float*)d_in[5];
    const float* w_ih   = (const float*)d_in[6];
    const float* w_hh   = (const float*)d_in[7];
    const float* b_ih   = (const float*)d_in[8];
    const float* b_hh   = (const float*)d_in[9];
    const float* fc_w   = (const float*)d_in[10];
    const float* fc_b   = (const float*)d_in[11];
    float* out = (float*)d_out;

    const int E = in_sizes[1];

    cudaFuncSetAttribute(mma_gemm2_kernel,
                         cudaFuncAttributeMaxDynamicSharedMemorySize, DB_SMEM_BYTES);

    float* base = nullptr;
    cudaGetSymbolAddress((void**)&base, s_scratch);
    float* p_h      = base + OFF_H;
    float* p_Wh     = base + OFF_WH;
    float* p_gh     = base + OFF_WH;   // alias: Wh dead after gather
    float* p_gx     = base + OFF_GX;
    float* p_pooled = base + OFF_POOL;

    int *p_deg, *p_rowptr, *p_cursor, *p_eidx;
    cudaGetSymbolAddress((void**)&p_deg, s_deg);
    cudaGetSymbolAddress((void**)&p_rowptr, s_rowptr);
    cudaGetSymbolAddress((void**)&p_cursor, s_cursor);
    cudaGetSymbolAddress((void**)&p_eidx, s_eidx);

    __nv_bfloat16 *p_Whi, *p_Wlo, *p_wihi, *p_wilo, *p_whhi, *p_whlo;
    __nv_bfloat16 *p_hhi, *p_hlo, *p_ahi, *p_alo;
    cudaGetSymbolAddress((void**)&p_Whi, s_Whi);
    cudaGetSymbolAddress((void**)&p_Wlo, s_Wlo);
    cudaGetSymbolAddress((void**)&p_wihi, s_wihi);
    cudaGetSymbolAddress((void**)&p_wilo, s_wilo);
    cudaGetSymbolAddress((void**)&p_whhi, s_whhi);
    cudaGetSymbolAddress((void**)&p_whlo, s_whlo);
    cudaGetSymbolAddress((void**)&p_hhi, s_hhi);
    cudaGetSymbolAddress((void**)&p_hlo, s_hlo);
    cudaGetSymbolAddress((void**)&p_ahi, s_ahi);
    cudaGetSymbolAddress((void**)&p_alo, s_alo);

    // ---- weight splits ----
    {
        int nW = LL * THX * HH;
        int nG = LL * H3 * HH;
        split_kernel<<<(nW + 255) / 256, 256>>>(W_lin, p_Whi, p_Wlo, nW);
        split_kernel<<<(nG + 255) / 256, 256>>>(w_ih, p_wihi, p_wilo, nG);
        split_kernel<<<(nG + 255) / 256, 256>>>(w_hh, p_whhi, p_whlo, nG);
    }

    // ---- CSR build ----
    zero_int_kernel<<<(NN + 255) / 256, 256>>>(p_deg, NN);
    hist_kernel<<<(E + 255) / 256, 256>>>(dst, p_deg, E);
    scan_kernel<<<1, 1024>>>(p_deg, p_rowptr, NN);
    cudaMemcpyAsync(p_cursor, p_rowptr, NN * sizeof(int), cudaMemcpyDeviceToDevice);
    fill_kernel<<<(E + 255) / 256, 256>>>(src, dst, etype, p_cursor, p_eidx, E);

    // ---- h = x ; h_hi/h_lo = split(x) ----
    size_t n4 = (size_t)NN * HH / 4;
    copy_kernel<<<(int)((n4 + 255) / 256), 256>>>(x, p_h, n4);
    split4_kernel<<<(int)((n4 + 255) / 256), 256>>>((const float4*)x, (uint2*)p_hhi,
                                                    (uint2*)p_hlo, (int)n4);

    dim3 grid_wh(THX / GBN, (NN + GBM - 1) / GBM);   // (8, 391)
    dim3 grid_g(H3 / GBN, (NN + GBM - 1) / GBM);     // (6, 391)
    int gather_blocks = (int)(((size_t)NN * 32 + 255) / 256);
    int gru_blocks = (int)((n4 + 255) / 256);

    for (int l = 0; l < LL; l++) {
        const float* blinL = b_lin + (size_t)l * THX;
        const float* bihL  = b_ih + (size_t)l * H3;
        const float* bhhL  = b_hh + (size_t)l * H3;
        const __nv_bfloat16* Whl  = p_Whi + (size_t)l * THX * HH;
        const __nv_bfloat16* Wll  = p_Wlo + (size_t)l * THX * HH;
        const __nv_bfloat16* wihl = p_wihi + (size_t)l * H3 * HH;
        const __nv_bfloat16* will = p_wilo + (size_t)l * H3 * HH;
        const __nv_bfloat16* whhl = p_whhi + (size_t)l * H3 * HH;
        const __nv_bfloat16* whll = p_whlo + (size_t)l * H3 * HH;

        for (int s = 0; s < SS; s++) {
            // Wh = h @ W^T + b_lin   [N, T*H]
            mma_gemm2_kernel<<<grid_wh, 256, DB_SMEM_BYTES>>>(
                p_hhi, p_hlo, Whl, Wll, blinL, p_Wh, NN, THX, HH);
            // a_hi/a_lo = split( gather of Wh over in-edges )  (no fp32 a)
            gather_kernel<<<gather_blocks, 256>>>(p_Wh, p_rowptr, p_eidx,
                                                  (uint2*)p_ahi, (uint2*)p_alo, NN);
            // gx = a @ w_ih^T + b_ih ; gh = h @ w_hh^T + b_hh (gh overwrites Wh)
            mma_gemm2_kernel<<<grid_g, 256, DB_SMEM_BYTES>>>(
                p_ahi, p_alo, wihl, will, bihL, p_gx, NN, H3, HH);
            mma_gemm2_kernel<<<grid_g, 256, DB_SMEM_BYTES>>>(
                p_hhi, p_hlo, whhl, whll, bhhL, p_gh, NN, H3, HH);
            // GRU gates: h fp32 in-place + h_hi/h_lo for next step's GEMMs
            gru_kernel<<<gru_blocks, 256>>>((const float4*)p_gx, (const float4*)p_gh,
                                            (float4*)p_h, (uint2*)p_hhi, (uint2*)p_hlo,
                                            (int)n4);
        }
    }

    // pooled mean + FC
    zero_kernel<<<1, 64>>>(p_pooled, HH / 4);
    pool_kernel<<<256, HH>>>(p_h, p_pooled, NN);
    fc_kernel<<<CC, 32>>>(p_pooled, fc_w, fc_b, out, 1.0f / (float)NN);
}